// round 6
// baseline (speedup 1.0000x reference)
#include <cuda_runtime.h>
#include <cuda_bf16.h>
#include <math.h>
#include <stdint.h>

// Problem dims (fixed by reference)
#define Bq 2
#define Tq 2048
#define Cq 768
#define Hq 12
#define HDq 64
#define Mrows (Bq*Tq)          // 4096
#define C3 (3*Cq)              // 2304
#define C4 (4*Cq)              // 3072

// ---------------- scratch (device globals; no allocations allowed) ----------
__device__ float g_ln1[Mrows*Cq];
__device__ float g_qkv[(size_t)Mrows*C3];
__device__ float g_att[Mrows*Cq];
__device__ float g_x1 [Mrows*Cq];
__device__ float g_ln2[Mrows*Cq];
__device__ float g_fc [(size_t)Mrows*C4];

// ---------------- common helpers --------------------------------------------
__device__ __forceinline__ float gelu_f(float x) {
    const float c = 0.7978845608028654f; // sqrt(2/pi)
    float t = tanhf(c * (x + 0.044715f * x * x * x));
    return 0.5f * x * (1.0f + t);
}

__device__ __forceinline__ float to_tf32(float x) {
    uint32_t r;
    asm("cvt.rna.tf32.f32 %0, %1;" : "=r"(r) : "f"(x));
    return __uint_as_float(r);
}

__device__ __forceinline__ void mma_tf32(float* c, const uint32_t* a, const uint32_t* b) {
    asm volatile(
        "mma.sync.aligned.m16n8k8.row.col.f32.tf32.tf32.f32 "
        "{%0,%1,%2,%3}, {%4,%5,%6,%7}, {%8,%9}, {%0,%1,%2,%3};\n"
        : "+f"(c[0]), "+f"(c[1]), "+f"(c[2]), "+f"(c[3])
        : "r"(a[0]), "r"(a[1]), "r"(a[2]), "r"(a[3]), "r"(b[0]), "r"(b[1]));
}

__device__ __forceinline__ void cpasync16(uint32_t dst, const void* src) {
    asm volatile("cp.async.cg.shared.global [%0], [%1], 16;" :: "r"(dst), "l"(src));
}

// ---------------- LayerNorm: one block per row ------------------------------
__global__ __launch_bounds__(256) void ln_kernel(const float* __restrict__ x,
                                                 const float* __restrict__ g,
                                                 const float* __restrict__ b,
                                                 float* __restrict__ o)
{
    int row = blockIdx.x;
    int tid = threadIdx.x;
    const float* xr = x + (size_t)row * Cq;
    float v0 = xr[tid], v1 = xr[tid + 256], v2 = xr[tid + 512];

    __shared__ float red[256];
    red[tid] = v0 + v1 + v2;
    __syncthreads();
    #pragma unroll
    for (int off = 128; off > 0; off >>= 1) {
        if (tid < off) red[tid] += red[tid + off];
        __syncthreads();
    }
    float mu = red[0] * (1.0f / Cq);
    __syncthreads();

    float d0 = v0 - mu, d1 = v1 - mu, d2 = v2 - mu;
    red[tid] = d0*d0 + d1*d1 + d2*d2;
    __syncthreads();
    #pragma unroll
    for (int off = 128; off > 0; off >>= 1) {
        if (tid < off) red[tid] += red[tid + off];
        __syncthreads();
    }
    float rstd = rsqrtf(red[0] * (1.0f / Cq) + 1e-5f);

    float* orow = o + (size_t)row * Cq;
    orow[tid      ] = d0 * rstd * g[tid      ] + b[tid      ];
    orow[tid + 256] = d1 * rstd * g[tid + 256] + b[tid + 256];
    orow[tid + 512] = d2 * rstd * g[tid + 512] + b[tid + 512];
}

// ---------------- tf32 tensor-core GEMM (unchanged) -------------------------
#define TBM 128
#define TBN 128
#define TBK 16
#define TPAD 8
#define TLDS (TBM + TPAD)

// FUSE: 1 = bias only, 2 = bias+gelu, 3 = bias+residual
template<int FUSE>
__global__ __launch_bounds__(256) void tgemm_kernel(const float* __restrict__ A,
                                                    const float* __restrict__ W,
                                                    const float* __restrict__ bias,
                                                    const float* __restrict__ res,
                                                    float* __restrict__ C,
                                                    int M, int N, int K)
{
    __shared__ float As[2][TBK][TLDS];
    __shared__ float Bs[2][TBK][TLDS];

    const int tid  = threadIdx.x;
    const int lane = tid & 31;
    const int w    = tid >> 5;
    const int g    = lane >> 2;
    const int cc   = lane & 3;
    const int wm   = w >> 2;
    const int wn   = w & 3;
    const int m_warp = wm * 64;
    const int n_warp = wn * 32;

    const int m0 = blockIdx.y * TBM;
    const int n0 = blockIdx.x * TBN;

    const int aRow0 = (tid + 0)   >> 2, aK0 = ((tid + 0)   & 3) << 2;
    const int aRow1 = (tid + 256) >> 2, aK1 = ((tid + 256) & 3) << 2;
    const int bRow0 = (tid + 0)   >> 5, bC0 = ((tid + 0)   & 31) << 2;
    const int bRow1 = (tid + 256) >> 5, bC1 = ((tid + 256) & 31) << 2;

    float acc[4][4][4] = {};
    const int ntiles = K / TBK;

    {
        float4 av0 = *(const float4*)&A[(size_t)(m0 + aRow0) * K + aK0];
        float4 av1 = *(const float4*)&A[(size_t)(m0 + aRow1) * K + aK1];
        float4 bv0 = *(const float4*)&W[(size_t)(bRow0) * N + n0 + bC0];
        float4 bv1 = *(const float4*)&W[(size_t)(bRow1) * N + n0 + bC1];
        As[0][aK0+0][aRow0] = to_tf32(av0.x); As[0][aK0+1][aRow0] = to_tf32(av0.y);
        As[0][aK0+2][aRow0] = to_tf32(av0.z); As[0][aK0+3][aRow0] = to_tf32(av0.w);
        As[0][aK1+0][aRow1] = to_tf32(av1.x); As[0][aK1+1][aRow1] = to_tf32(av1.y);
        As[0][aK1+2][aRow1] = to_tf32(av1.z); As[0][aK1+3][aRow1] = to_tf32(av1.w);
        float4 t0 = make_float4(to_tf32(bv0.x), to_tf32(bv0.y), to_tf32(bv0.z), to_tf32(bv0.w));
        float4 t1 = make_float4(to_tf32(bv1.x), to_tf32(bv1.y), to_tf32(bv1.z), to_tf32(bv1.w));
        *(float4*)&Bs[0][bRow0][bC0] = t0;
        *(float4*)&Bs[0][bRow1][bC1] = t1;
    }
    __syncthreads();

    for (int t = 0; t < ntiles; t++) {
        const int cur = t & 1;
        const int nxt = cur ^ 1;

        float4 av0, av1, bv0, bv1;
        const bool has_next = (t + 1 < ntiles);
        if (has_next) {
            const int k0 = (t + 1) * TBK;
            av0 = *(const float4*)&A[(size_t)(m0 + aRow0) * K + k0 + aK0];
            av1 = *(const float4*)&A[(size_t)(m0 + aRow1) * K + k0 + aK1];
            bv0 = *(const float4*)&W[(size_t)(k0 + bRow0) * N + n0 + bC0];
            bv1 = *(const float4*)&W[(size_t)(k0 + bRow1) * N + n0 + bC1];
        }

        #pragma unroll
        for (int kb = 0; kb < 2; kb++) {
            const int kk = kb * 8;
            uint32_t afr[4][4];
            uint32_t bfr[4][2];
            #pragma unroll
            for (int mf = 0; mf < 4; mf++) {
                const int mb = m_warp + mf * 16;
                afr[mf][0] = __float_as_uint(As[cur][kk + cc    ][mb + g    ]);
                afr[mf][1] = __float_as_uint(As[cur][kk + cc    ][mb + g + 8]);
                afr[mf][2] = __float_as_uint(As[cur][kk + cc + 4][mb + g    ]);
                afr[mf][3] = __float_as_uint(As[cur][kk + cc + 4][mb + g + 8]);
            }
            #pragma unroll
            for (int nf = 0; nf < 4; nf++) {
                const int nb = n_warp + nf * 8;
                bfr[nf][0] = __float_as_uint(Bs[cur][kk + cc    ][nb + g]);
                bfr[nf][1] = __float_as_uint(Bs[cur][kk + cc + 4][nb + g]);
            }
            #pragma unroll
            for (int mf = 0; mf < 4; mf++)
                #pragma unroll
                for (int nf = 0; nf < 4; nf++)
                    mma_tf32(acc[mf][nf], afr[mf], bfr[nf]);
        }

        if (has_next) {
            As[nxt][aK0+0][aRow0] = to_tf32(av0.x); As[nxt][aK0+1][aRow0] = to_tf32(av0.y);
            As[nxt][aK0+2][aRow0] = to_tf32(av0.z); As[nxt][aK0+3][aRow0] = to_tf32(av0.w);
            As[nxt][aK1+0][aRow1] = to_tf32(av1.x); As[nxt][aK1+1][aRow1] = to_tf32(av1.y);
            As[nxt][aK1+2][aRow1] = to_tf32(av1.z); As[nxt][aK1+3][aRow1] = to_tf32(av1.w);
            float4 t0 = make_float4(to_tf32(bv0.x), to_tf32(bv0.y), to_tf32(bv0.z), to_tf32(bv0.w));
            float4 t1 = make_float4(to_tf32(bv1.x), to_tf32(bv1.y), to_tf32(bv1.z), to_tf32(bv1.w));
            *(float4*)&Bs[nxt][bRow0][bC0] = t0;
            *(float4*)&Bs[nxt][bRow1][bC1] = t1;
        }
        __syncthreads();
    }

    #pragma unroll
    for (int mf = 0; mf < 4; mf++) {
        #pragma unroll
        for (int nf = 0; nf < 4; nf++) {
            const int n  = n0 + n_warp + nf * 8 + 2 * cc;
            const int r0 = m0 + m_warp + mf * 16 + g;
            const int r1 = r0 + 8;
            float b0 = bias[n], b1 = bias[n + 1];
            float v00 = acc[mf][nf][0] + b0;
            float v01 = acc[mf][nf][1] + b1;
            float v10 = acc[mf][nf][2] + b0;
            float v11 = acc[mf][nf][3] + b1;
            if (FUSE == 2) {
                v00 = gelu_f(v00); v01 = gelu_f(v01);
                v10 = gelu_f(v10); v11 = gelu_f(v11);
            }
            if (FUSE == 3) {
                const float2 r0v = *(const float2*)&res[(size_t)r0 * N + n];
                const float2 r1v = *(const float2*)&res[(size_t)r1 * N + n];
                v00 += r0v.x; v01 += r0v.y;
                v10 += r1v.x; v11 += r1v.y;
            }
            *(float2*)&C[(size_t)r0 * N + n] = make_float2(v00, v01);
            *(float2*)&C[(size_t)r1 * N + n] = make_float2(v10, v11);
        }
    }
}

// ---------------- tensor-core flash attention v3 -----------------------------
// 256 threads (8 warps), Q-tile 128 (warp w owns rows 16w..16w+15), K/V-tile 64,
// cp.async double-buffered K/V, Q frags in registers, causal warp-skip,
// reversed CTA order (long blocks first). 2 CTAs/SM.
#define ATQ 128
#define ATK 64
#define KS_TILE (64*64)     // floats per K buffer (stride 64, chunk-XOR swizzle)
#define VS_STR  72
#define VS_TILE (64*VS_STR)
#define PS_STR  68
#define PS_TILE (ATQ*PS_STR)
#define ATT_SMEM ((2*KS_TILE + 2*VS_TILE + PS_TILE) * 4)  // 104192 B

__device__ __forceinline__ void attn_issue_kv(const float* __restrict__ qkv,
                                              int b, int h, int k0,
                                              float* KsBuf, float* VsBuf, int tid)
{
    #pragma unroll
    for (int i = 0; i < 4; i++) {
        const int e  = tid + i * 256;     // 0..1023
        const int r  = e >> 4;
        const int ch = e & 15;
        const float* src = qkv + ((size_t)(b * Tq + k0 + r)) * C3 + h * HDq + ch * 4;
        uint32_t dk = (uint32_t)__cvta_generic_to_shared(
            &KsBuf[r * 64 + ((ch ^ (r & 7)) << 2)]);
        uint32_t dv = (uint32_t)__cvta_generic_to_shared(
            &VsBuf[r * VS_STR + (ch << 2)]);
        cpasync16(dk, src + Cq);
        cpasync16(dv, src + 2 * Cq);
    }
}

__global__ __launch_bounds__(256, 2) void fattn_kernel(const float* __restrict__ qkv,
                                                       float* __restrict__ y)
{
    extern __shared__ float sm[];
    float* Ks = sm;                               // [2][64][64] swizzled
    float* Vs = sm + 2 * KS_TILE;                 // [2][64][72]
    float* Ps = sm + 2 * KS_TILE + 2 * VS_TILE;   // [128][68]; Q staging first

    const int tid  = threadIdx.x;
    const int lane = tid & 31;
    const int w    = tid >> 5;
    const int g    = lane >> 2;
    const int cc   = lane & 3;
    const int b    = blockIdx.z, h = blockIdx.y;
    const int q0   = (int)(gridDim.x - 1 - blockIdx.x) * ATQ;  // long blocks first
    const int mrow = w * 16;

    // prologue: start async load of K/V tile 0 immediately
    attn_issue_kv(qkv, b, h, 0, Ks, Vs, tid);
    asm volatile("cp.async.commit_group;" ::: "memory");

    // stage Q (scaled, tf32) into Ps region with K-style swizzle, then to regs
    for (int e = tid; e < ATQ * 16; e += 256) {
        const int r = e >> 4, ch = e & 15;
        const float* p = qkv + ((size_t)(b * Tq + q0 + r)) * C3 + h * HDq + ch * 4;
        float4 v = *(const float4*)p;
        float* d = &Ps[r * 64 + ((ch ^ (r & 7)) << 2)];
        d[0] = to_tf32(v.x * 0.125f); d[1] = to_tf32(v.y * 0.125f);
        d[2] = to_tf32(v.z * 0.125f); d[3] = to_tf32(v.w * 0.125f);
    }
    __syncthreads();

    uint32_t qf[8][4];
    #pragma unroll
    for (int kb = 0; kb < 8; kb++) {
        const int ch0 = kb * 2;
        qf[kb][0] = __float_as_uint(Ps[(mrow + g    ) * 64 + (((ch0    ) ^ g) << 2) + cc]);
        qf[kb][1] = __float_as_uint(Ps[(mrow + g + 8) * 64 + (((ch0    ) ^ g) << 2) + cc]);
        qf[kb][2] = __float_as_uint(Ps[(mrow + g    ) * 64 + (((ch0 + 1) ^ g) << 2) + cc]);
        qf[kb][3] = __float_as_uint(Ps[(mrow + g + 8) * 64 + (((ch0 + 1) ^ g) << 2) + cc]);
    }

    float of[8][4] = {};
    float m_a = -1e30f, m_b = -1e30f, l_a = 0.0f, l_b = 0.0f;

    const int ntiles = (q0 + ATQ) / ATK;   // keys 0 .. q0+127
    for (int t = 0; t < ntiles; t++) {
        const int buf = t & 1;
        const int k0  = t * ATK;
        const bool has_next = (t + 1) < ntiles;
        if (has_next) {
            attn_issue_kv(qkv, b, h, (t + 1) * ATK,
                          Ks + (buf ^ 1) * KS_TILE, Vs + (buf ^ 1) * VS_TILE, tid);
            asm volatile("cp.async.commit_group;" ::: "memory");
            asm volatile("cp.async.wait_group 1;" ::: "memory");
        } else {
            asm volatile("cp.async.wait_group 0;" ::: "memory");
        }
        __syncthreads();   // tile t ready; prev compute done

        // causal: this warp's rows are q0+mrow..q0+mrow+15
        if (k0 <= q0 + mrow + 15) {
            const float* KsB = Ks + buf * KS_TILE;
            const float* VsB = Vs + buf * VS_TILE;

            // ---- S = Q @ K^T
            float sf[8][4] = {};
            #pragma unroll
            for (int kb = 0; kb < 8; kb++) {
                const int ch0 = kb * 2;
                #pragma unroll
                for (int nf = 0; nf < 8; nf++) {
                    const int rk = nf * 8 + g;
                    uint32_t bb[2];
                    bb[0] = __float_as_uint(KsB[rk * 64 + (((ch0    ) ^ g) << 2) + cc]);
                    bb[1] = __float_as_uint(KsB[rk * 64 + (((ch0 + 1) ^ g) << 2) + cc]);
                    mma_tf32(sf[nf], qf[kb], bb);
                }
            }

            if (k0 + ATK - 1 > q0 + mrow) {   // diagonal: mask key k0+col > q0+row
                const int ta = q0 - k0 + mrow + g;       // threshold for row a
                const int tb = ta + 8;
                #pragma unroll
                for (int nf = 0; nf < 8; nf++) {
                    const int col0 = nf * 8 + 2 * cc;
                    if (col0     > ta) sf[nf][0] = -1e30f;
                    if (col0 + 1 > ta) sf[nf][1] = -1e30f;
                    if (col0     > tb) sf[nf][2] = -1e30f;
                    if (col0 + 1 > tb) sf[nf][3] = -1e30f;
                }
            }

            // ---- tile row max
            float mt_a = -1e30f, mt_b = -1e30f;
            #pragma unroll
            for (int nf = 0; nf < 8; nf++) {
                mt_a = fmaxf(mt_a, fmaxf(sf[nf][0], sf[nf][1]));
                mt_b = fmaxf(mt_b, fmaxf(sf[nf][2], sf[nf][3]));
            }
            mt_a = fmaxf(mt_a, __shfl_xor_sync(0xffffffffu, mt_a, 1));
            mt_a = fmaxf(mt_a, __shfl_xor_sync(0xffffffffu, mt_a, 2));
            mt_b = fmaxf(mt_b, __shfl_xor_sync(0xffffffffu, mt_b, 1));
            mt_b = fmaxf(mt_b, __shfl_xor_sync(0xffffffffu, mt_b, 2));

            // ---- online softmax update
            const float mn_a = fmaxf(m_a, mt_a), mn_b = fmaxf(m_b, mt_b);
            const float ca = __expf(m_a - mn_a), cb = __expf(m_b - mn_b);
            m_a = mn_a; m_b = mn_b;
            l_a *= ca; l_b *= cb;
            #pragma unroll
            for (int nd = 0; nd < 8; nd++) {
                of[nd][0] *= ca; of[nd][1] *= ca;
                of[nd][2] *= cb; of[nd][3] *= cb;
            }

            float sa = 0.0f, sb = 0.0f;
            #pragma unroll
            for (int nf = 0; nf < 8; nf++) {
                float p0 = to_tf32(__expf(sf[nf][0] - m_a));
                float p1 = to_tf32(__expf(sf[nf][1] - m_a));
                float p2 = to_tf32(__expf(sf[nf][2] - m_b));
                float p3 = to_tf32(__expf(sf[nf][3] - m_b));
                sa += p0 + p1; sb += p2 + p3;
                *(float2*)&Ps[(mrow + g    ) * PS_STR + nf * 8 + 2 * cc] = make_float2(p0, p1);
                *(float2*)&Ps[(mrow + g + 8) * PS_STR + nf * 8 + 2 * cc] = make_float2(p2, p3);
            }
            sa += __shfl_xor_sync(0xffffffffu, sa, 1);
            sa += __shfl_xor_sync(0xffffffffu, sa, 2);
            sb += __shfl_xor_sync(0xffffffffu, sb, 1);
            sb += __shfl_xor_sync(0xffffffffu, sb, 2);
            l_a += sa; l_b += sb;
            __syncwarp();      // Ps rows mrow..mrow+15 are warp-private

            // ---- O += P @ V
            #pragma unroll
            for (int kb = 0; kb < 8; kb++) {
                const int kk = kb * 8;
                uint32_t a[4];
                a[0] = __float_as_uint(Ps[(mrow + g    ) * PS_STR + kk + cc    ]);
                a[1] = __float_as_uint(Ps[(mrow + g + 8) * PS_STR + kk + cc    ]);
                a[2] = __float_as_uint(Ps[(mrow + g    ) * PS_STR + kk + cc + 4]);
                a[3] = __float_as_uint(Ps[(mrow + g + 8) * PS_STR + kk + cc + 4]);
                #pragma unroll
                for (int nd = 0; nd < 8; nd++) {
                    uint32_t bb[2];
                    bb[0] = __float_as_uint(VsB[(kk + cc    ) * VS_STR + nd * 8 + g]);
                    bb[1] = __float_as_uint(VsB[(kk + cc + 4) * VS_STR + nd * 8 + g]);
                    mma_tf32(of[nd], a, bb);
                }
            }
        }
        __syncthreads();       // all warps done with buf before refill
    }

    const float ia = 1.0f / l_a, ib = 1.0f / l_b;
    const int ra = q0 + mrow + g, rb = ra + 8;
    #pragma unroll
    for (int nd = 0; nd < 8; nd++) {
        const int col = h * HDq + nd * 8 + 2 * cc;
        *(float2*)&y[((size_t)(b * Tq) + ra) * Cq + col] =
            make_float2(of[nd][0] * ia, of[nd][1] * ia);
        *(float2*)&y[((size_t)(b * Tq) + rb) * Cq + col] =
            make_float2(of[nd][2] * ib, of[nd][3] * ib);
    }
}

// ---------------- launch ----------------------------------------------------
extern "C" void kernel_launch(void* const* d_in, const int* in_sizes, int n_in,
                              void* d_out, int out_size)
{
    (void)in_sizes; (void)n_in; (void)out_size;
    const float* x           = (const float*)d_in[0];
    const float* ln1_g       = (const float*)d_in[1];
    const float* ln1_b       = (const float*)d_in[2];
    const float* w_attn      = (const float*)d_in[3];
    const float* b_attn      = (const float*)d_in[4];
    const float* w_attn_proj = (const float*)d_in[5];
    const float* b_attn_proj = (const float*)d_in[6];
    const float* ln2_g       = (const float*)d_in[7];
    const float* ln2_b       = (const float*)d_in[8];
    const float* w_fc        = (const float*)d_in[9];
    const float* b_fc        = (const float*)d_in[10];
    const float* w_mlp_proj  = (const float*)d_in[11];
    const float* b_mlp_proj  = (const float*)d_in[12];
    float* out = (float*)d_out;

    float *ln1, *qkv, *att, *x1, *ln2, *fc;
    cudaGetSymbolAddress((void**)&ln1, g_ln1);
    cudaGetSymbolAddress((void**)&qkv, g_qkv);
    cudaGetSymbolAddress((void**)&att, g_att);
    cudaGetSymbolAddress((void**)&x1,  g_x1);
    cudaGetSymbolAddress((void**)&ln2, g_ln2);
    cudaGetSymbolAddress((void**)&fc,  g_fc);

    cudaFuncSetAttribute(fattn_kernel,
                         cudaFuncAttributeMaxDynamicSharedMemorySize, ATT_SMEM);

    // 1. LN1
    ln_kernel<<<Mrows, 256>>>(x, ln1_g, ln1_b, ln1);
    // 2. QKV = ln1 @ w_attn + b_attn          [4096, 2304]
    tgemm_kernel<1><<<dim3(C3 / TBN, Mrows / TBM), 256>>>(ln1, w_attn, b_attn,
                                                          nullptr, qkv, Mrows, C3, Cq);
    // 3. attention -> att [4096, 768]
    fattn_kernel<<<dim3(Tq / ATQ, Hq, Bq), 256, ATT_SMEM>>>(qkv, att);
    // 4. x1 = x + att @ w_attn_proj + b_attn_proj
    tgemm_kernel<3><<<dim3(Cq / TBN, Mrows / TBM), 256>>>(att, w_attn_proj, b_attn_proj,
                                                          x, x1, Mrows, Cq, Cq);
    // 5. LN2
    ln_kernel<<<Mrows, 256>>>(x1, ln2_g, ln2_b, ln2);
    // 6. fc = gelu(ln2 @ w_fc + b_fc)         [4096, 3072]
    tgemm_kernel<2><<<dim3(C4 / TBN, Mrows / TBM), 256>>>(ln2, w_fc, b_fc,
                                                          nullptr, fc, Mrows, C4, Cq);
    // 7. out = x1 + fc @ w_mlp_proj + b_mlp_proj
    tgemm_kernel<3><<<dim3(Cq / TBN, Mrows / TBM), 256>>>(fc, w_mlp_proj, b_mlp_proj,
                                                          x1, out, Mrows, Cq, C4);
}

// round 7
// speedup vs baseline: 1.1351x; 1.1351x over previous
#include <cuda_runtime.h>
#include <cuda_bf16.h>
#include <math.h>
#include <stdint.h>

// Problem dims (fixed by reference)
#define Bq 2
#define Tq 2048
#define Cq 768
#define Hq 12
#define HDq 64
#define Mrows (Bq*Tq)          // 4096
#define C3 (3*Cq)              // 2304
#define C4 (4*Cq)              // 3072

// ---------------- scratch (device globals; no allocations allowed) ----------
__device__ float g_ln1[Mrows*Cq];
__device__ float g_qkv[(size_t)Mrows*C3];
__device__ float g_att[Mrows*Cq];
__device__ float g_x1 [Mrows*Cq];
__device__ float g_ln2[Mrows*Cq];
__device__ float g_fc [(size_t)Mrows*C4];

// ---------------- common helpers --------------------------------------------
__device__ __forceinline__ float gelu_f(float x) {
    const float c = 0.7978845608028654f; // sqrt(2/pi)
    float t = tanhf(c * (x + 0.044715f * x * x * x));
    return 0.5f * x * (1.0f + t);
}

__device__ __forceinline__ float to_tf32(float x) {
    uint32_t r;
    asm("cvt.rna.tf32.f32 %0, %1;" : "=r"(r) : "f"(x));
    return __uint_as_float(r);
}

__device__ __forceinline__ void mma_tf32(float* c, const uint32_t* a, const uint32_t* b) {
    asm volatile(
        "mma.sync.aligned.m16n8k8.row.col.f32.tf32.tf32.f32 "
        "{%0,%1,%2,%3}, {%4,%5,%6,%7}, {%8,%9}, {%0,%1,%2,%3};\n"
        : "+f"(c[0]), "+f"(c[1]), "+f"(c[2]), "+f"(c[3])
        : "r"(a[0]), "r"(a[1]), "r"(a[2]), "r"(a[3]), "r"(b[0]), "r"(b[1]));
}

__device__ __forceinline__ void cpasync16(uint32_t dst, const void* src) {
    asm volatile("cp.async.cg.shared.global [%0], [%1], 16;" :: "r"(dst), "l"(src));
}

// ---------------- LayerNorm: one block per row ------------------------------
__global__ __launch_bounds__(256) void ln_kernel(const float* __restrict__ x,
                                                 const float* __restrict__ g,
                                                 const float* __restrict__ b,
                                                 float* __restrict__ o)
{
    int row = blockIdx.x;
    int tid = threadIdx.x;
    const float* xr = x + (size_t)row * Cq;
    float v0 = xr[tid], v1 = xr[tid + 256], v2 = xr[tid + 512];

    __shared__ float red[256];
    red[tid] = v0 + v1 + v2;
    __syncthreads();
    #pragma unroll
    for (int off = 128; off > 0; off >>= 1) {
        if (tid < off) red[tid] += red[tid + off];
        __syncthreads();
    }
    float mu = red[0] * (1.0f / Cq);
    __syncthreads();

    float d0 = v0 - mu, d1 = v1 - mu, d2 = v2 - mu;
    red[tid] = d0*d0 + d1*d1 + d2*d2;
    __syncthreads();
    #pragma unroll
    for (int off = 128; off > 0; off >>= 1) {
        if (tid < off) red[tid] += red[tid + off];
        __syncthreads();
    }
    float rstd = rsqrtf(red[0] * (1.0f / Cq) + 1e-5f);

    float* orow = o + (size_t)row * Cq;
    orow[tid      ] = d0 * rstd * g[tid      ] + b[tid      ];
    orow[tid + 256] = d1 * rstd * g[tid + 256] + b[tid + 256];
    orow[tid + 512] = d2 * rstd * g[tid + 512] + b[tid + 512];
}

// ---------------- tf32 GEMM v2: 4-stage cp.async pipeline -------------------
// 128x128 tile, BK=16, 256 threads = 8 warps, warp 64x32 (4x4 m16n8k8).
// A staged row-major [m][k] stride 20 (conflict-free a-frag), B [k][n] stride 136.
// mma consumes raw fp32 bits as tf32 (truncation) — no cvt needed.
#define GS 4
#define ASTRIDE 20
#define BSTRIDE 136
#define A_TILE_F (128*ASTRIDE)          // 2560 floats
#define B_TILE_F (16*BSTRIDE)           // 2176 floats
#define STAGE_F  (A_TILE_F + B_TILE_F)  // 4736 floats
#define TG_SMEM  (GS*STAGE_F*4)         // 75776 bytes

// FUSE: 1 = bias only, 2 = bias+gelu, 3 = bias+residual
template<int FUSE>
__global__ __launch_bounds__(256, 2) void tgemm_kernel(const float* __restrict__ A,
                                                       const float* __restrict__ W,
                                                       const float* __restrict__ bias,
                                                       const float* __restrict__ res,
                                                       float* __restrict__ C,
                                                       int M, int N, int K)
{
    extern __shared__ float tsm[];

    const int tid  = threadIdx.x;
    const int lane = tid & 31;
    const int w    = tid >> 5;
    const int g    = lane >> 2;
    const int cc   = lane & 3;
    const int m_warp = (w >> 2) * 64;
    const int n_warp = (w & 3) * 32;

    const int m0 = blockIdx.y * 128;
    const int n0 = blockIdx.x * 128;

    // loader indices: A 512 chunks (2/thread), B 512 chunks (2/thread)
    const int aR = tid >> 2;            // 0..63 (and +64)
    const int aK = (tid & 3) << 2;      // 0,4,8,12
    const int bR = tid >> 5;            // 0..7  (and +8)
    const int bC = (tid & 31) << 2;     // 0..124

    const int ntiles = K / 16;

    // per-thread smem dst addresses (stage 0 base)
    uint32_t a_dst0 = (uint32_t)__cvta_generic_to_shared(&tsm[aR * ASTRIDE + aK]);
    uint32_t a_dst1 = (uint32_t)__cvta_generic_to_shared(&tsm[(aR + 64) * ASTRIDE + aK]);
    uint32_t b_dst0 = (uint32_t)__cvta_generic_to_shared(&tsm[A_TILE_F + bR * BSTRIDE + bC]);
    uint32_t b_dst1 = (uint32_t)__cvta_generic_to_shared(&tsm[A_TILE_F + (bR + 8) * BSTRIDE + bC]);

    const float* a_src0 = &A[(size_t)(m0 + aR) * K + aK];
    const float* a_src1 = &A[(size_t)(m0 + aR + 64) * K + aK];
    const float* b_src0 = &W[(size_t)bR * N + n0 + bC];
    const float* b_src1 = &W[(size_t)(bR + 8) * N + n0 + bC];

    // prologue: issue stages 0..2
    #pragma unroll
    for (int t = 0; t < 3; t++) {
        const uint32_t so = (uint32_t)(t * STAGE_F * 4);
        cpasync16(a_dst0 + so, a_src0 + t * 16);
        cpasync16(a_dst1 + so, a_src1 + t * 16);
        cpasync16(b_dst0 + so, b_src0 + (size_t)t * 16 * N);
        cpasync16(b_dst1 + so, b_src1 + (size_t)t * 16 * N);
        asm volatile("cp.async.commit_group;" ::: "memory");
    }

    float acc[4][4][4] = {};

    for (int t = 0; t < ntiles; t++) {
        asm volatile("cp.async.wait_group 2;" ::: "memory");
        __syncthreads();

        // issue tile t+3 into slot (t+3)&3 (was computed at iter t-1)
        if (t + 3 < ntiles) {
            const int s = (t + 3) & 3;
            const uint32_t so = (uint32_t)(s * STAGE_F * 4);
            const int k0 = (t + 3) * 16;
            cpasync16(a_dst0 + so, a_src0 + k0);
            cpasync16(a_dst1 + so, a_src1 + k0);
            cpasync16(b_dst0 + so, b_src0 + (size_t)k0 * N);
            cpasync16(b_dst1 + so, b_src1 + (size_t)k0 * N);
        }
        asm volatile("cp.async.commit_group;" ::: "memory");

        const float* As = tsm + (t & 3) * STAGE_F;
        const float* Bs = As + A_TILE_F;

        #pragma unroll
        for (int kb = 0; kb < 2; kb++) {
            const int kk = kb * 8;
            uint32_t afr[4][4];
            uint32_t bfr[4][2];
            #pragma unroll
            for (int mf = 0; mf < 4; mf++) {
                const int mb = m_warp + mf * 16;
                afr[mf][0] = __float_as_uint(As[(mb + g    ) * ASTRIDE + kk + cc    ]);
                afr[mf][1] = __float_as_uint(As[(mb + g + 8) * ASTRIDE + kk + cc    ]);
                afr[mf][2] = __float_as_uint(As[(mb + g    ) * ASTRIDE + kk + cc + 4]);
                afr[mf][3] = __float_as_uint(As[(mb + g + 8) * ASTRIDE + kk + cc + 4]);
            }
            #pragma unroll
            for (int nf = 0; nf < 4; nf++) {
                const int nb = n_warp + nf * 8;
                bfr[nf][0] = __float_as_uint(Bs[(kk + cc    ) * BSTRIDE + nb + g]);
                bfr[nf][1] = __float_as_uint(Bs[(kk + cc + 4) * BSTRIDE + nb + g]);
            }
            #pragma unroll
            for (int mf = 0; mf < 4; mf++)
                #pragma unroll
                for (int nf = 0; nf < 4; nf++)
                    mma_tf32(acc[mf][nf], afr[mf], bfr[nf]);
        }
    }

    // epilogue
    #pragma unroll
    for (int mf = 0; mf < 4; mf++) {
        #pragma unroll
        for (int nf = 0; nf < 4; nf++) {
            const int n  = n0 + n_warp + nf * 8 + 2 * cc;
            const int r0 = m0 + m_warp + mf * 16 + g;
            const int r1 = r0 + 8;
            float b0 = bias[n], b1 = bias[n + 1];
            float v00 = acc[mf][nf][0] + b0;
            float v01 = acc[mf][nf][1] + b1;
            float v10 = acc[mf][nf][2] + b0;
            float v11 = acc[mf][nf][3] + b1;
            if (FUSE == 2) {
                v00 = gelu_f(v00); v01 = gelu_f(v01);
                v10 = gelu_f(v10); v11 = gelu_f(v11);
            }
            if (FUSE == 3) {
                const float2 r0v = *(const float2*)&res[(size_t)r0 * N + n];
                const float2 r1v = *(const float2*)&res[(size_t)r1 * N + n];
                v00 += r0v.x; v01 += r0v.y;
                v10 += r1v.x; v11 += r1v.y;
            }
            *(float2*)&C[(size_t)r0 * N + n] = make_float2(v00, v01);
            *(float2*)&C[(size_t)r1 * N + n] = make_float2(v10, v11);
        }
    }
}

// ---------------- tensor-core flash attention (unchanged from R5) -----------
#define ATQ 128
#define ATK 64
#define KS_TILE (64*64)
#define VS_STR  72
#define VS_TILE (64*VS_STR)
#define PS_STR  68
#define PS_TILE (ATQ*PS_STR)
#define ATT_SMEM ((2*KS_TILE + 2*VS_TILE + PS_TILE) * 4)  // 104192 B

__device__ __forceinline__ void attn_issue_kv(const float* __restrict__ qkv,
                                              int b, int h, int k0,
                                              float* KsBuf, float* VsBuf, int tid)
{
    #pragma unroll
    for (int i = 0; i < 4; i++) {
        const int e  = tid + i * 256;
        const int r  = e >> 4;
        const int ch = e & 15;
        const float* src = qkv + ((size_t)(b * Tq + k0 + r)) * C3 + h * HDq + ch * 4;
        uint32_t dk = (uint32_t)__cvta_generic_to_shared(
            &KsBuf[r * 64 + ((ch ^ (r & 7)) << 2)]);
        uint32_t dv = (uint32_t)__cvta_generic_to_shared(
            &VsBuf[r * VS_STR + (ch << 2)]);
        cpasync16(dk, src + Cq);
        cpasync16(dv, src + 2 * Cq);
    }
}

__global__ __launch_bounds__(256, 2) void fattn_kernel(const float* __restrict__ qkv,
                                                       float* __restrict__ y)
{
    extern __shared__ float sm[];
    float* Ks = sm;
    float* Vs = sm + 2 * KS_TILE;
    float* Ps = sm + 2 * KS_TILE + 2 * VS_TILE;

    const int tid  = threadIdx.x;
    const int lane = tid & 31;
    const int w    = tid >> 5;
    const int g    = lane >> 2;
    const int cc   = lane & 3;
    const int b    = blockIdx.z, h = blockIdx.y;
    const int q0   = (int)(gridDim.x - 1 - blockIdx.x) * ATQ;
    const int mrow = w * 16;

    attn_issue_kv(qkv, b, h, 0, Ks, Vs, tid);
    asm volatile("cp.async.commit_group;" ::: "memory");

    for (int e = tid; e < ATQ * 16; e += 256) {
        const int r = e >> 4, ch = e & 15;
        const float* p = qkv + ((size_t)(b * Tq + q0 + r)) * C3 + h * HDq + ch * 4;
        float4 v = *(const float4*)p;
        float* d = &Ps[r * 64 + ((ch ^ (r & 7)) << 2)];
        d[0] = to_tf32(v.x * 0.125f); d[1] = to_tf32(v.y * 0.125f);
        d[2] = to_tf32(v.z * 0.125f); d[3] = to_tf32(v.w * 0.125f);
    }
    __syncthreads();

    uint32_t qf[8][4];
    #pragma unroll
    for (int kb = 0; kb < 8; kb++) {
        const int ch0 = kb * 2;
        qf[kb][0] = __float_as_uint(Ps[(mrow + g    ) * 64 + (((ch0    ) ^ g) << 2) + cc]);
        qf[kb][1] = __float_as_uint(Ps[(mrow + g + 8) * 64 + (((ch0    ) ^ g) << 2) + cc]);
        qf[kb][2] = __float_as_uint(Ps[(mrow + g    ) * 64 + (((ch0 + 1) ^ g) << 2) + cc]);
        qf[kb][3] = __float_as_uint(Ps[(mrow + g + 8) * 64 + (((ch0 + 1) ^ g) << 2) + cc]);
    }

    float of[8][4] = {};
    float m_a = -1e30f, m_b = -1e30f, l_a = 0.0f, l_b = 0.0f;

    const int ntiles = (q0 + ATQ) / ATK;
    for (int t = 0; t < ntiles; t++) {
        const int buf = t & 1;
        const int k0  = t * ATK;
        const bool has_next = (t + 1) < ntiles;
        if (has_next) {
            attn_issue_kv(qkv, b, h, (t + 1) * ATK,
                          Ks + (buf ^ 1) * KS_TILE, Vs + (buf ^ 1) * VS_TILE, tid);
            asm volatile("cp.async.commit_group;" ::: "memory");
            asm volatile("cp.async.wait_group 1;" ::: "memory");
        } else {
            asm volatile("cp.async.wait_group 0;" ::: "memory");
        }
        __syncthreads();

        if (k0 <= q0 + mrow + 15) {
            const float* KsB = Ks + buf * KS_TILE;
            const float* VsB = Vs + buf * VS_TILE;

            float sf[8][4] = {};
            #pragma unroll
            for (int kb = 0; kb < 8; kb++) {
                const int ch0 = kb * 2;
                #pragma unroll
                for (int nf = 0; nf < 8; nf++) {
                    const int rk = nf * 8 + g;
                    uint32_t bb[2];
                    bb[0] = __float_as_uint(KsB[rk * 64 + (((ch0    ) ^ g) << 2) + cc]);
                    bb[1] = __float_as_uint(KsB[rk * 64 + (((ch0 + 1) ^ g) << 2) + cc]);
                    mma_tf32(sf[nf], qf[kb], bb);
                }
            }

            if (k0 + ATK - 1 > q0 + mrow) {
                const int ta = q0 - k0 + mrow + g;
                const int tb = ta + 8;
                #pragma unroll
                for (int nf = 0; nf < 8; nf++) {
                    const int col0 = nf * 8 + 2 * cc;
                    if (col0     > ta) sf[nf][0] = -1e30f;
                    if (col0 + 1 > ta) sf[nf][1] = -1e30f;
                    if (col0     > tb) sf[nf][2] = -1e30f;
                    if (col0 + 1 > tb) sf[nf][3] = -1e30f;
                }
            }

            float mt_a = -1e30f, mt_b = -1e30f;
            #pragma unroll
            for (int nf = 0; nf < 8; nf++) {
                mt_a = fmaxf(mt_a, fmaxf(sf[nf][0], sf[nf][1]));
                mt_b = fmaxf(mt_b, fmaxf(sf[nf][2], sf[nf][3]));
            }
            mt_a = fmaxf(mt_a, __shfl_xor_sync(0xffffffffu, mt_a, 1));
            mt_a = fmaxf(mt_a, __shfl_xor_sync(0xffffffffu, mt_a, 2));
            mt_b = fmaxf(mt_b, __shfl_xor_sync(0xffffffffu, mt_b, 1));
            mt_b = fmaxf(mt_b, __shfl_xor_sync(0xffffffffu, mt_b, 2));

            const float mn_a = fmaxf(m_a, mt_a), mn_b = fmaxf(m_b, mt_b);
            const float ca = __expf(m_a - mn_a), cb = __expf(m_b - mn_b);
            m_a = mn_a; m_b = mn_b;
            l_a *= ca; l_b *= cb;
            #pragma unroll
            for (int nd = 0; nd < 8; nd++) {
                of[nd][0] *= ca; of[nd][1] *= ca;
                of[nd][2] *= cb; of[nd][3] *= cb;
            }

            float sa = 0.0f, sb = 0.0f;
            #pragma unroll
            for (int nf = 0; nf < 8; nf++) {
                float p0 = to_tf32(__expf(sf[nf][0] - m_a));
                float p1 = to_tf32(__expf(sf[nf][1] - m_a));
                float p2 = to_tf32(__expf(sf[nf][2] - m_b));
                float p3 = to_tf32(__expf(sf[nf][3] - m_b));
                sa += p0 + p1; sb += p2 + p3;
                *(float2*)&Ps[(mrow + g    ) * PS_STR + nf * 8 + 2 * cc] = make_float2(p0, p1);
                *(float2*)&Ps[(mrow + g + 8) * PS_STR + nf * 8 + 2 * cc] = make_float2(p2, p3);
            }
            sa += __shfl_xor_sync(0xffffffffu, sa, 1);
            sa += __shfl_xor_sync(0xffffffffu, sa, 2);
            sb += __shfl_xor_sync(0xffffffffu, sb, 1);
            sb += __shfl_xor_sync(0xffffffffu, sb, 2);
            l_a += sa; l_b += sb;
            __syncwarp();

            #pragma unroll
            for (int kb = 0; kb < 8; kb++) {
                const int kk = kb * 8;
                uint32_t a[4];
                a[0] = __float_as_uint(Ps[(mrow + g    ) * PS_STR + kk + cc    ]);
                a[1] = __float_as_uint(Ps[(mrow + g + 8) * PS_STR + kk + cc    ]);
                a[2] = __float_as_uint(Ps[(mrow + g    ) * PS_STR + kk + cc + 4]);
                a[3] = __float_as_uint(Ps[(mrow + g + 8) * PS_STR + kk + cc + 4]);
                #pragma unroll
                for (int nd = 0; nd < 8; nd++) {
                    uint32_t bb[2];
                    bb[0] = __float_as_uint(VsB[(kk + cc    ) * VS_STR + nd * 8 + g]);
                    bb[1] = __float_as_uint(VsB[(kk + cc + 4) * VS_STR + nd * 8 + g]);
                    mma_tf32(of[nd], a, bb);
                }
            }
        }
        __syncthreads();
    }

    const float ia = 1.0f / l_a, ib = 1.0f / l_b;
    const int ra = q0 + mrow + g, rb = ra + 8;
    #pragma unroll
    for (int nd = 0; nd < 8; nd++) {
        const int col = h * HDq + nd * 8 + 2 * cc;
        *(float2*)&y[((size_t)(b * Tq) + ra) * Cq + col] =
            make_float2(of[nd][0] * ia, of[nd][1] * ia);
        *(float2*)&y[((size_t)(b * Tq) + rb) * Cq + col] =
            make_float2(of[nd][2] * ib, of[nd][3] * ib);
    }
}

// ---------------- launch ----------------------------------------------------
extern "C" void kernel_launch(void* const* d_in, const int* in_sizes, int n_in,
                              void* d_out, int out_size)
{
    (void)in_sizes; (void)n_in; (void)out_size;
    const float* x           = (const float*)d_in[0];
    const float* ln1_g       = (const float*)d_in[1];
    const float* ln1_b       = (const float*)d_in[2];
    const float* w_attn      = (const float*)d_in[3];
    const float* b_attn      = (const float*)d_in[4];
    const float* w_attn_proj = (const float*)d_in[5];
    const float* b_attn_proj = (const float*)d_in[6];
    const float* ln2_g       = (const float*)d_in[7];
    const float* ln2_b       = (const float*)d_in[8];
    const float* w_fc        = (const float*)d_in[9];
    const float* b_fc        = (const float*)d_in[10];
    const float* w_mlp_proj  = (const float*)d_in[11];
    const float* b_mlp_proj  = (const float*)d_in[12];
    float* out = (float*)d_out;

    float *ln1, *qkv, *att, *x1, *ln2, *fc;
    cudaGetSymbolAddress((void**)&ln1, g_ln1);
    cudaGetSymbolAddress((void**)&qkv, g_qkv);
    cudaGetSymbolAddress((void**)&att, g_att);
    cudaGetSymbolAddress((void**)&x1,  g_x1);
    cudaGetSymbolAddress((void**)&ln2, g_ln2);
    cudaGetSymbolAddress((void**)&fc,  g_fc);

    cudaFuncSetAttribute(fattn_kernel,
                         cudaFuncAttributeMaxDynamicSharedMemorySize, ATT_SMEM);
    cudaFuncSetAttribute(tgemm_kernel<1>,
                         cudaFuncAttributeMaxDynamicSharedMemorySize, TG_SMEM);
    cudaFuncSetAttribute(tgemm_kernel<2>,
                         cudaFuncAttributeMaxDynamicSharedMemorySize, TG_SMEM);
    cudaFuncSetAttribute(tgemm_kernel<3>,
                         cudaFuncAttributeMaxDynamicSharedMemorySize, TG_SMEM);

    // 1. LN1
    ln_kernel<<<Mrows, 256>>>(x, ln1_g, ln1_b, ln1);
    // 2. QKV = ln1 @ w_attn + b_attn          [4096, 2304]
    tgemm_kernel<1><<<dim3(C3 / 128, Mrows / 128), 256, TG_SMEM>>>(ln1, w_attn, b_attn,
                                                                   nullptr, qkv, Mrows, C3, Cq);
    // 3. attention -> att [4096, 768]
    fattn_kernel<<<dim3(Tq / ATQ, Hq, Bq), 256, ATT_SMEM>>>(qkv, att);
    // 4. x1 = x + att @ w_attn_proj + b_attn_proj
    tgemm_kernel<3><<<dim3(Cq / 128, Mrows / 128), 256, TG_SMEM>>>(att, w_attn_proj, b_attn_proj,
                                                                   x, x1, Mrows, Cq, Cq);
    // 5. LN2
    ln_kernel<<<Mrows, 256>>>(x1, ln2_g, ln2_b, ln2);
    // 6. fc = gelu(ln2 @ w_fc + b_fc)         [4096, 3072]
    tgemm_kernel<2><<<dim3(C4 / 128, Mrows / 128), 256, TG_SMEM>>>(ln2, w_fc, b_fc,
                                                                   nullptr, fc, Mrows, C4, Cq);
    // 7. out = x1 + fc @ w_mlp_proj + b_mlp_proj
    tgemm_kernel<3><<<dim3(Cq / 128, Mrows / 128), 256, TG_SMEM>>>(fc, w_mlp_proj, b_mlp_proj,
                                                                   x1, out, Mrows, Cq, C4);
}